// round 9
// baseline (speedup 1.0000x reference)
#include <cuda_runtime.h>

#define Bn 32
#define Tn 128
#define In 256
#define Hn 256
#define IH 512
#define On 128
#define NBLK 256      // persistent blocks; 32 KB smem, <=128 regs => 2 blocks/SM
#define NTHR 256      // 8 warps

typedef unsigned long long ull;

__device__ float g_h[2][Bn * Hn];   // ping-pong hidden state
__device__ unsigned g_bar;          // monotonic grid-barrier counter (1 inc/block/step)

// ---------------------------------------------------------------------------
__global__ void init_kernel()
{
    int i = blockIdx.x * blockDim.x + threadIdx.x;
    if (i == 0) g_bar = 0u;
    for (int k = i; k < Bn * Hn; k += gridDim.x * blockDim.x) g_h[0][k] = 0.f;
}

// ---------------------------------------------------------------------------
__device__ __forceinline__ float warp_sum(float v)
{
#pragma unroll
    for (int o = 16; o > 0; o >>= 1) v += __shfl_xor_sync(0xffffffffu, v, o);
    return v;
}
__device__ __forceinline__ float tanh_fast(float v)
{
    float r; asm("tanh.approx.f32 %0, %1;" : "=f"(r) : "f"(v)); return r;
}
__device__ __forceinline__ unsigned ld_acquire(const unsigned* p)
{
    unsigned v;
    asm volatile("ld.acquire.gpu.global.u32 %0, [%1];" : "=r"(v) : "l"(p) : "memory");
    return v;
}
__device__ __forceinline__ void red_release(unsigned* p)
{
    asm volatile("red.release.gpu.global.add.u32 [%0], 1;" :: "l"(p) : "memory");
}
__device__ __forceinline__ unsigned atom_inc_cta_shared(unsigned* p)
{
    unsigned old;
    unsigned addr = (unsigned)__cvta_generic_to_shared(p);
    asm volatile("atom.acq_rel.cta.shared.add.u32 %0, [%1], 1;"
                 : "=r"(old) : "r"(addr) : "memory");
    return old;
}
// ---- packed f32x2 primitives ----
__device__ __forceinline__ ull f2_add(ull a, ull b)
{ ull d; asm("add.rn.f32x2 %0, %1, %2;" : "=l"(d) : "l"(a), "l"(b)); return d; }
__device__ __forceinline__ ull f2_sub(ull a, ull b)
{ ull d; asm("sub.rn.f32x2 %0, %1, %2;" : "=l"(d) : "l"(a), "l"(b)); return d; }
__device__ __forceinline__ ull f2_mul(ull a, ull b)
{ ull d; asm("mul.rn.f32x2 %0, %1, %2;" : "=l"(d) : "l"(a), "l"(b)); return d; }
__device__ __forceinline__ ull f2_fma(ull a, ull b, ull c)
{ ull d; asm("fma.rn.f32x2 %0, %1, %2, %3;" : "=l"(d) : "l"(a), "l"(b), "l"(c)); return d; }
__device__ __forceinline__ ull f2_bcast(float v)
{ ull d; asm("mov.b64 %0, {%1, %1};" : "=l"(d) : "f"(v)); return d; }
__device__ __forceinline__ float f2_fold(ull v)
{ float lo, hi; asm("mov.b64 {%0, %1}, %2;" : "=f"(lo), "=f"(hi) : "l"(v)); return lo + hi; }
__device__ __forceinline__ ulonglong2 ldnc2(const ulonglong2* p)
{ ulonglong2 v; asm("ld.global.nc.v2.u64 {%0,%1}, [%2];" : "=l"(v.x), "=l"(v.y) : "l"(p)); return v; }
__device__ __forceinline__ ulonglong2 ldcg2(const ulonglong2* p)
{ ulonglong2 v; asm volatile("ld.global.cg.v2.u64 {%0,%1}, [%2];" : "=l"(v.x), "=l"(v.y) : "l"(p)); return v; }

// ---------------------------------------------------------------------------
// Persistent kernel, 2 blocks/SM. Block owns h-row bid x 32 batches.
// Warp w handles batches w + {0,8,16,24}; lane slice: 16B unit k*32+lane.
//
// F storage split:
//   x-part (f in [0,256))  -> smem F_sm [32 rows][64 u2]  (32 KB)
//   h-part (f in [256,512))-> REGISTERS as tw23 = W + F (8 floats/lane/task)
// B1 (critical): dot from dxp + ha,hb x tw23 regs -> tanh -> h store.
// B2 (off-path): x-part writeback via smem; h-part update in regs
// (F2 = tw2 - w2); next-step ss/dx partials fused.
// ---------------------------------------------------------------------------
__global__ __launch_bounds__(NTHR, 2) void persist_kernel(
    const float* __restrict__ x,
    const float* __restrict__ Wl,
    const float* __restrict__ Wg,
    const float* __restrict__ W,
    const float* __restrict__ bias,
    const float* __restrict__ Wout,
    const float* __restrict__ bout,
    float* __restrict__ out)
{
    extern __shared__ float F_sm[];                    // 32 KB (x-part of F)
    ulonglong2* __restrict__ F2 = (ulonglong2*)F_sm;   // [32][64] 16B units
    __shared__ unsigned s_cnt;

    const int tid  = threadIdx.x;
    const int wid  = tid >> 5, lane = tid & 31;
    const int bi0  = wid;                      // 0..7
    const int h    = blockIdx.x;

    if (tid == 0) s_cnt = 0u;

    // Pinned: full W row slice (16 regs) + h-part of l,g (16 regs).
    ulonglong2 w2[4], l2h[2], g2h[2];
    {
        const ulonglong2* Wp = (const ulonglong2*)(W  + (size_t)h * IH);
        const ulonglong2* Lp = (const ulonglong2*)(Wl + (size_t)h * IH);
        const ulonglong2* Gp = (const ulonglong2*)(Wg + (size_t)h * IH);
#pragma unroll
        for (int k = 0; k < 4; k++) w2[k] = ldnc2(Wp + k * 32 + lane);
        l2h[0] = ldnc2(Lp + 64 + lane); l2h[1] = ldnc2(Lp + 96 + lane);
        g2h[0] = ldnc2(Gp + 64 + lane); g2h[1] = ldnc2(Gp + 96 + lane);
    }
    const float bia = __ldg(bias + h);

    // Zero x-part F rows in smem; h-part tw23 regs start at W (F=0).
    ull t2x[4], t2y[4], t3x[4], t3y[4];
    {
        ulonglong2 z; z.x = 0ull; z.y = 0ull;
#pragma unroll
        for (int u = 0; u < 4; u++) {
            ulonglong2* Fr = F2 + (bi0 + u * 8) * 64;
            Fr[lane] = z; Fr[32 + lane] = z;
            t2x[u] = w2[2].x; t2y[u] = w2[2].y;
            t3x[u] = w2[3].x; t3y[u] = w2[3].y;
        }
    }

    // Bootstrap partials for t=0 (F=0 => tw=W).
    float ssp[4], rn[4], hn[4];
    ull dxp[4];
    {
        ull sw = f2_mul(w2[0].x, w2[0].x);
        sw = f2_fma(w2[0].y, w2[0].y, sw);
        sw = f2_fma(w2[1].x, w2[1].x, sw);
        sw = f2_fma(w2[1].y, w2[1].y, sw);
        sw = f2_fma(w2[2].x, w2[2].x, sw);
        sw = f2_fma(w2[2].y, w2[2].y, sw);
        sw = f2_fma(w2[3].x, w2[3].x, sw);
        sw = f2_fma(w2[3].y, w2[3].y, sw);
        const float ssw = f2_fold(sw);
#pragma unroll
        for (int u = 0; u < 4; u++) {
            const int bi = bi0 + u * 8;
            const ulonglong2* xr = (const ulonglong2*)(x + (size_t)bi * Tn * In);
            ulonglong2 xv0 = ldnc2(xr + lane);
            ulonglong2 xv1 = ldnc2(xr + 32 + lane);
            ull a = f2_mul(xv0.x, w2[0].x);
            a = f2_fma(xv0.y, w2[0].y, a);
            a = f2_fma(xv1.x, w2[1].x, a);
            a = f2_fma(xv1.y, w2[1].y, a);
            ssp[u] = ssw;
            dxp[u] = a;
        }
    }

    for (int t = 0; t < Tn; t++) {
        const ulonglong2* __restrict__ hin = (const ulonglong2*)g_h[t & 1];
        float* __restrict__ hout = g_h[(t & 1) ^ 1];
        const int tn = (t + 1 < Tn) ? t + 1 : t;

        // ss reduce + rsqrt (off critical path; 4 interleaved chains).
#pragma unroll
        for (int o = 16; o > 0; o >>= 1) {
            ssp[0] += __shfl_xor_sync(0xffffffffu, ssp[0], o);
            ssp[1] += __shfl_xor_sync(0xffffffffu, ssp[1], o);
            ssp[2] += __shfl_xor_sync(0xffffffffu, ssp[2], o);
            ssp[3] += __shfl_xor_sync(0xffffffffu, ssp[3], o);
        }
#pragma unroll
        for (int u = 0; u < 4; u++) rn[u] = rsqrtf(ssp[u]);

        // ---------- wait: h(t-1) published by all blocks ----------
        if (tid == 0) {
            const unsigned target = (unsigned)NBLK * (unsigned)t;
            while (ld_acquire(&g_bar) < target) __nanosleep(32);
        }
        __syncthreads();

        // ---------- B1 (critical span): dot from regs -> h_new -> publish ----------
        ulonglong2 ha[4], hb[4];
#pragma unroll
        for (int u = 0; u < 4; u++) {          // 8 LDGs up front (MLP)
            const int bi = bi0 + u * 8;
            ha[u] = ldcg2(hin + bi * 64 + lane);
            hb[u] = ldcg2(hin + bi * 64 + 32 + lane);
        }
#pragma unroll
        for (int u = 0; u < 4; u++) {
            const int bi = bi0 + u * 8;
            ull acc = dxp[u];
            acc = f2_fma(ha[u].x, t2x[u], acc);
            acc = f2_fma(ha[u].y, t2y[u], acc);
            acc = f2_fma(hb[u].x, t3x[u], acc);
            acc = f2_fma(hb[u].y, t3y[u], acc);
            float tot = warp_sum(f2_fold(acc));
            hn[u] = tanh_fast(tot + bia) * rn[u];
            if (lane == 0) hout[bi * Hn + h] = hn[u];
        }

        // ---------- ARRIVE (hierarchical: smem acq_rel -> 1 global red) ----------
        if (lane == 0) {
            unsigned old = atom_inc_cta_shared(&s_cnt);
            if ((old & 7u) == 7u) red_release(&g_bar);
        }

        // ---------- B2 (off critical path) ----------
        // x-part l,g reloaded once per step (L1 hits; not pinned to save regs).
        ulonglong2 l0, l1, g0, g1;
        {
            const ulonglong2* Lp = (const ulonglong2*)(Wl + (size_t)h * IH);
            const ulonglong2* Gp = (const ulonglong2*)(Wg + (size_t)h * IH);
            l0 = ldnc2(Lp + lane); l1 = ldnc2(Lp + 32 + lane);
            g0 = ldnc2(Gp + lane); g1 = ldnc2(Gp + 32 + lane);
        }
#pragma unroll
        for (int u = 0; u < 4; u++) {
            const int bi = bi0 + u * 8;
            const ull rr2 = f2_bcast(rn[u]);
            const ull hv2 = f2_bcast(hn[u]);

            // ---- h-part: pure register update ----
            // F2 = tw2 - w2;  n2 = l2h*(F2*rn) + g2h*(h_in*hn);  tw2' = w2 + n2
            ull F2a = f2_sub(t2x[u], w2[2].x);
            ull F2b = f2_sub(t2y[u], w2[2].y);
            ull F3a = f2_sub(t3x[u], w2[3].x);
            ull F3b = f2_sub(t3y[u], w2[3].y);
            ull n2a = f2_fma(g2h[0].x, f2_mul(ha[u].x, hv2), f2_mul(l2h[0].x, f2_mul(F2a, rr2)));
            ull n2b = f2_fma(g2h[0].y, f2_mul(ha[u].y, hv2), f2_mul(l2h[0].y, f2_mul(F2b, rr2)));
            ull n3a = f2_fma(g2h[1].x, f2_mul(hb[u].x, hv2), f2_mul(l2h[1].x, f2_mul(F3a, rr2)));
            ull n3b = f2_fma(g2h[1].y, f2_mul(hb[u].y, hv2), f2_mul(l2h[1].y, f2_mul(F3b, rr2)));
            t2x[u] = f2_add(w2[2].x, n2a);
            t2y[u] = f2_add(w2[2].y, n2b);
            t3x[u] = f2_add(w2[3].x, n3a);
            t3y[u] = f2_add(w2[3].y, n3b);

            // ---- x-part: smem read/modify/write ----
            const ulonglong2* __restrict__ xr =
                (const ulonglong2*)(x + ((size_t)bi * Tn + t) * In);
            ulonglong2 xv0 = ldnc2(xr + lane);          // L1 hits
            ulonglong2 xv1 = ldnc2(xr + 32 + lane);
            ulonglong2* __restrict__ Fr = F2 + bi * 64;
            ulonglong2 Fv0 = Fr[lane], Fv1 = Fr[32 + lane];

            ulonglong2 n0, n1;
            n0.x = f2_fma(g0.x, f2_mul(xv0.x, hv2), f2_mul(l0.x, f2_mul(Fv0.x, rr2)));
            n0.y = f2_fma(g0.y, f2_mul(xv0.y, hv2), f2_mul(l0.y, f2_mul(Fv0.y, rr2)));
            n1.x = f2_fma(g1.x, f2_mul(xv1.x, hv2), f2_mul(l1.x, f2_mul(Fv1.x, rr2)));
            n1.y = f2_fma(g1.y, f2_mul(xv1.y, hv2), f2_mul(l1.y, f2_mul(Fv1.y, rr2)));
            Fr[lane] = n0;
            Fr[32 + lane] = n1;

            // ---- next-step partials ----
            ull t0x = f2_add(w2[0].x, n0.x), t0y = f2_add(w2[0].y, n0.y);
            ull t1x = f2_add(w2[1].x, n1.x), t1y = f2_add(w2[1].y, n1.y);

            ull ss = f2_mul(t0x, t0x);
            ss = f2_fma(t0y, t0y, ss);
            ss = f2_fma(t1x, t1x, ss);
            ss = f2_fma(t1y, t1y, ss);
            ss = f2_fma(t2x[u], t2x[u], ss);
            ss = f2_fma(t2y[u], t2y[u], ss);
            ss = f2_fma(t3x[u], t3x[u], ss);
            ss = f2_fma(t3y[u], t3y[u], ss);
            ssp[u] = f2_fold(ss);

            const ulonglong2* __restrict__ xq =
                (const ulonglong2*)(x + ((size_t)bi * Tn + tn) * In);
            ulonglong2 xa = ldnc2(xq + lane);
            ulonglong2 xb = ldnc2(xq + 32 + lane);
            ull dx = f2_mul(xa.x, t0x);
            dx = f2_fma(xa.y, t0y, dx);
            dx = f2_fma(xb.x, t1x, dx);
            dx = f2_fma(xb.y, t1y, dx);
            dxp[u] = dx;
        }
    }

    // ---- F writeout: x-part from smem, h-part from tw23 regs ----
    float* __restrict__ Fout = out + Bn * On + Bn * Hn;
    ulonglong2* __restrict__ Fo2 = (ulonglong2*)Fout;
#pragma unroll
    for (int u = 0; u < 4; u++) {
        const int bb = bi0 + u * 8;
        const size_t grow = (size_t)(bb * Hn + h) * (IH / 4);
        const ulonglong2* Fr = F2 + bb * 64;
        Fo2[grow + lane] = Fr[lane];
        Fo2[grow + 32 + lane] = Fr[32 + lane];
        ulonglong2 o2, o3;
        o2.x = f2_sub(t2x[u], w2[2].x); o2.y = f2_sub(t2y[u], w2[2].y);
        o3.x = f2_sub(t3x[u], w2[3].x); o3.y = f2_sub(t3y[u], w2[3].y);
        Fo2[grow + 64 + lane] = o2;
        Fo2[grow + 96 + lane] = o3;
    }

    // ---- epilogue: needs all blocks' final h ----
    if (blockIdx.x < 64) {
        if (tid == 0) {
            const unsigned target = (unsigned)NBLK * (unsigned)Tn;
            while (ld_acquire(&g_bar) < target) __nanosleep(32);
        }
        __syncthreads();
    }

    if (blockIdx.x < 32) {
        const int b = blockIdx.x;
        for (int i = tid; i < Hn; i += NTHR)
            F_sm[i] = __ldcg(&g_h[0][b * Hn + i]);   // T even -> final h in buf 0
        __syncthreads();
        const float4* hv4 = (const float4*)F_sm;
        for (int o = wid; o < On; o += 8) {
            const float4* wr = (const float4*)(Wout + (size_t)o * Hn);
            float acc = 0.f;
#pragma unroll
            for (int k = 0; k < 2; k++) {
                int j4 = k * 32 + lane;
                float4 w = __ldg(wr + j4);
                float4 hv = hv4[j4];
                acc += w.x * hv.x + w.y * hv.y + w.z * hv.z + w.w * hv.w;
            }
            acc = warp_sum(acc);
            if (lane == 0) out[b * On + o] = acc + __ldg(bout + o);
        }
    } else if (blockIdx.x < 64) {
        const int b = blockIdx.x - 32;
        for (int i = tid; i < Hn; i += NTHR)
            out[Bn * On + b * Hn + i] = __ldcg(&g_h[0][b * Hn + i]);
    }
}

// ---------------------------------------------------------------------------
extern "C" void kernel_launch(void* const* d_in, const int* in_sizes, int n_in,
                              void* d_out, int out_size)
{
    const float* sentence = (const float*)d_in[0];
    const float* Wl   = (const float*)d_in[1];
    const float* Wg   = (const float*)d_in[2];
    const float* W    = (const float*)d_in[3];
    const float* bias = (const float*)d_in[4];
    const float* Wout = (const float*)d_in[5];
    const float* bout = (const float*)d_in[6];
    float* out = (float*)d_out;

    const int smem = 32 * (In) * sizeof(float);  // 32 rows x 256 floats = 32768 B
    cudaFuncSetAttribute(persist_kernel, cudaFuncAttributeMaxDynamicSharedMemorySize, smem);

    init_kernel<<<32, 256>>>();
    persist_kernel<<<NBLK, NTHR, smem>>>(sentence, Wl, Wg, W, bias, Wout, bout, out);
}

// round 10
// speedup vs baseline: 1.0364x; 1.0364x over previous
#include <cuda_runtime.h>

#define Bn 32
#define Tn 128
#define In 256
#define Hn 256
#define IH 512
#define On 128
#define NBLK 256      // persistent blocks; 32 KB smem, <=128 regs => 2 blocks/SM
#define NTHR 256      // 8 warps

typedef unsigned long long ull;

__device__ float g_h[3][Bn * Hn];   // TRIPLE-buffered hidden state
__device__ unsigned g_bar;          // monotonic grid-barrier counter (1 inc/block/step)

// ---------------------------------------------------------------------------
__global__ void init_kernel()
{
    int i = blockIdx.x * blockDim.x + threadIdx.x;
    if (i == 0) g_bar = 0u;
    for (int k = i; k < Bn * Hn; k += gridDim.x * blockDim.x) g_h[0][k] = 0.f;
}

// ---------------------------------------------------------------------------
__device__ __forceinline__ float warp_sum(float v)
{
#pragma unroll
    for (int o = 16; o > 0; o >>= 1) v += __shfl_xor_sync(0xffffffffu, v, o);
    return v;
}
__device__ __forceinline__ float tanh_fast(float v)
{
    float r; asm("tanh.approx.f32 %0, %1;" : "=f"(r) : "f"(v)); return r;
}
__device__ __forceinline__ unsigned ld_acquire(const unsigned* p)
{
    unsigned v;
    asm volatile("ld.acquire.gpu.global.u32 %0, [%1];" : "=r"(v) : "l"(p) : "memory");
    return v;
}
__device__ __forceinline__ void red_release(unsigned* p)
{
    asm volatile("red.release.gpu.global.add.u32 [%0], 1;" :: "l"(p) : "memory");
}
__device__ __forceinline__ unsigned atom_inc_cta_shared(unsigned* p)
{
    unsigned old;
    unsigned addr = (unsigned)__cvta_generic_to_shared(p);
    asm volatile("atom.acq_rel.cta.shared.add.u32 %0, [%1], 1;"
                 : "=r"(old) : "r"(addr) : "memory");
    return old;
}
// ---- packed f32x2 primitives ----
__device__ __forceinline__ ull f2_add(ull a, ull b)
{ ull d; asm("add.rn.f32x2 %0, %1, %2;" : "=l"(d) : "l"(a), "l"(b)); return d; }
__device__ __forceinline__ ull f2_sub(ull a, ull b)
{ ull d; asm("sub.rn.f32x2 %0, %1, %2;" : "=l"(d) : "l"(a), "l"(b)); return d; }
__device__ __forceinline__ ull f2_mul(ull a, ull b)
{ ull d; asm("mul.rn.f32x2 %0, %1, %2;" : "=l"(d) : "l"(a), "l"(b)); return d; }
__device__ __forceinline__ ull f2_fma(ull a, ull b, ull c)
{ ull d; asm("fma.rn.f32x2 %0, %1, %2, %3;" : "=l"(d) : "l"(a), "l"(b), "l"(c)); return d; }
__device__ __forceinline__ ull f2_bcast(float v)
{ ull d; asm("mov.b64 %0, {%1, %1};" : "=l"(d) : "f"(v)); return d; }
__device__ __forceinline__ float f2_fold(ull v)
{ float lo, hi; asm("mov.b64 {%0, %1}, %2;" : "=f"(lo), "=f"(hi) : "l"(v)); return lo + hi; }
__device__ __forceinline__ ulonglong2 ldnc2(const ulonglong2* p)
{ ulonglong2 v; asm("ld.global.nc.v2.u64 {%0,%1}, [%2];" : "=l"(v.x), "=l"(v.y) : "l"(p)); return v; }
__device__ __forceinline__ ulonglong2 ldcg2(const ulonglong2* p)
{ ulonglong2 v; asm volatile("ld.global.cg.v2.u64 {%0,%1}, [%2];" : "=l"(v.x), "=l"(v.y) : "l"(p)); return v; }

// ---------------------------------------------------------------------------
// Persistent kernel, 2 blocks/SM. Block owns h-row bid x 32 batches.
// Warp w handles batches w + {0,8,16,24}; lane slice: 16B unit k*32+lane.
//
// F storage: x-part in smem (32 KB); h-part carried in REGISTERS as
// tw23 = W + F (32 regs). h is TRIPLE-buffered in global, so B2 may re-load
// h(t-1) after the arrive (the buffer is not rewritten until step t+2) —
// ha/hb are NOT kept live across the arrive (this is what spilled in R9).
// B1 (critical): pure-register dot -> tanh -> h store. Zero LDS on the span.
// ---------------------------------------------------------------------------
__global__ __launch_bounds__(NTHR, 2) void persist_kernel(
    const float* __restrict__ x,
    const float* __restrict__ Wl,
    const float* __restrict__ Wg,
    const float* __restrict__ W,
    const float* __restrict__ bias,
    const float* __restrict__ Wout,
    const float* __restrict__ bout,
    float* __restrict__ out)
{
    extern __shared__ float F_sm[];                    // 32 KB (x-part of F)
    ulonglong2* __restrict__ F2 = (ulonglong2*)F_sm;   // [32][64] 16B units
    __shared__ unsigned s_cnt;

    const int tid  = threadIdx.x;
    const int wid  = tid >> 5, lane = tid & 31;
    const int bi0  = wid;                      // 0..7
    const int h    = blockIdx.x;

    if (tid == 0) s_cnt = 0u;

    // Pinned for the whole kernel: full W row slice (16 regs) + bias.
    ull w2x[4], w2y[4];
    {
        const ulonglong2* Wp = (const ulonglong2*)(W + (size_t)h * IH);
#pragma unroll
        for (int k = 0; k < 4; k++) {
            ulonglong2 v = ldnc2(Wp + k * 32 + lane);
            w2x[k] = v.x; w2y[k] = v.y;
        }
    }
    const float bia = __ldg(bias + h);

    // Zero x-part F rows in smem; h-part tw23 regs start at W (F=0).
    ull t2x[4], t2y[4], t3x[4], t3y[4];
    {
        ulonglong2 z; z.x = 0ull; z.y = 0ull;
#pragma unroll
        for (int u = 0; u < 4; u++) {
            ulonglong2* Fr = F2 + (bi0 + u * 8) * 64;
            Fr[lane] = z; Fr[32 + lane] = z;
            t2x[u] = w2x[2]; t2y[u] = w2y[2];
            t3x[u] = w2x[3]; t3y[u] = w2y[3];
        }
    }

    // Bootstrap partials for t=0 (F=0 => tw=W).
    float ssp[4], rn[4], hn[4];
    ull dxp[4];
    {
        ull sw = f2_mul(w2x[0], w2x[0]);
        sw = f2_fma(w2y[0], w2y[0], sw);
        sw = f2_fma(w2x[1], w2x[1], sw);
        sw = f2_fma(w2y[1], w2y[1], sw);
        sw = f2_fma(w2x[2], w2x[2], sw);
        sw = f2_fma(w2y[2], w2y[2], sw);
        sw = f2_fma(w2x[3], w2x[3], sw);
        sw = f2_fma(w2y[3], w2y[3], sw);
        const float ssw = f2_fold(sw);
#pragma unroll
        for (int u = 0; u < 4; u++) {
            const int bi = bi0 + u * 8;
            const ulonglong2* xr = (const ulonglong2*)(x + (size_t)bi * Tn * In);
            ulonglong2 xv0 = ldnc2(xr + lane);
            ulonglong2 xv1 = ldnc2(xr + 32 + lane);
            ull a = f2_mul(xv0.x, w2x[0]);
            a = f2_fma(xv0.y, w2y[0], a);
            a = f2_fma(xv1.x, w2x[1], a);
            a = f2_fma(xv1.y, w2y[1], a);
            ssp[u] = ssw;
            dxp[u] = a;
        }
    }

    int p0 = 0;                                // t % 3
    for (int t = 0; t < Tn; t++) {
        const int p1 = (p0 == 2) ? 0 : p0 + 1;
        const ulonglong2* __restrict__ hin = (const ulonglong2*)g_h[p0];
        float* __restrict__ hout = g_h[p1];
        const int tn = (t + 1 < Tn) ? t + 1 : t;

        // ss reduce + rsqrt (off critical path; 4 interleaved chains).
#pragma unroll
        for (int o = 16; o > 0; o >>= 1) {
            ssp[0] += __shfl_xor_sync(0xffffffffu, ssp[0], o);
            ssp[1] += __shfl_xor_sync(0xffffffffu, ssp[1], o);
            ssp[2] += __shfl_xor_sync(0xffffffffu, ssp[2], o);
            ssp[3] += __shfl_xor_sync(0xffffffffu, ssp[3], o);
        }
#pragma unroll
        for (int u = 0; u < 4; u++) rn[u] = rsqrtf(ssp[u]);

        // ---------- wait: h(t-1) published by all blocks ----------
        if (tid == 0) {
            const unsigned target = (unsigned)NBLK * (unsigned)t;
            while (ld_acquire(&g_bar) < target) __nanosleep(32);
        }
        __syncthreads();

        // ---------- B1 (critical span): pure-register dot -> publish ----------
        {
            ulonglong2 ha[4], hb[4];
#pragma unroll
            for (int u = 0; u < 4; u++) {      // 8 LDGs up front (MLP)
                const int bi = bi0 + u * 8;
                ha[u] = ldcg2(hin + bi * 64 + lane);
                hb[u] = ldcg2(hin + bi * 64 + 32 + lane);
            }
#pragma unroll
            for (int u = 0; u < 4; u++) {
                const int bi = bi0 + u * 8;
                ull acc = dxp[u];
                acc = f2_fma(ha[u].x, t2x[u], acc);
                acc = f2_fma(ha[u].y, t2y[u], acc);
                acc = f2_fma(hb[u].x, t3x[u], acc);
                acc = f2_fma(hb[u].y, t3y[u], acc);
                float tot = warp_sum(f2_fold(acc));
                hn[u] = tanh_fast(tot + bia) * rn[u];
                if (lane == 0) hout[bi * Hn + h] = hn[u];
            }
        }   // ha/hb die here — not live across the arrive.

        // ---------- ARRIVE (hierarchical: smem acq_rel -> 1 global red) ----------
        if (lane == 0) {
            unsigned old = atom_inc_cta_shared(&s_cnt);
            if ((old & 7u) == 7u) red_release(&g_bar);
        }

        // ---------- B2 (off critical path) ----------
        // All lambda/gamma slices reloaded per step (L1 hits; saves 32 regs).
        ulonglong2 l0, l1, g0, g1, l2, l3, g2, g3;
        {
            const ulonglong2* Lp = (const ulonglong2*)(Wl + (size_t)h * IH);
            const ulonglong2* Gp = (const ulonglong2*)(Wg + (size_t)h * IH);
            l0 = ldnc2(Lp + lane);      l1 = ldnc2(Lp + 32 + lane);
            l2 = ldnc2(Lp + 64 + lane); l3 = ldnc2(Lp + 96 + lane);
            g0 = ldnc2(Gp + lane);      g1 = ldnc2(Gp + 32 + lane);
            g2 = ldnc2(Gp + 64 + lane); g3 = ldnc2(Gp + 96 + lane);
        }
#pragma unroll
        for (int u = 0; u < 4; u++) {
            const int bi = bi0 + u * 8;
            const ull rr2 = f2_bcast(rn[u]);
            const ull hv2 = f2_bcast(hn[u]);

            // Re-load h(t-1) — safe: triple buffer not rewritten until t+2.
            ulonglong2 hha = ldcg2(hin + bi * 64 + lane);
            ulonglong2 hhb = ldcg2(hin + bi * 64 + 32 + lane);

            // ---- h-part: pure register update ----
            // F2 = tw2 - w2;  n2 = l2*(F2*rn) + g2*(h_in*hn);  tw2' = w2 + n2
            ull F2a = f2_sub(t2x[u], w2x[2]);
            ull F2b = f2_sub(t2y[u], w2y[2]);
            ull F3a = f2_sub(t3x[u], w2x[3]);
            ull F3b = f2_sub(t3y[u], w2y[3]);
            ull n2a = f2_fma(g2.x, f2_mul(hha.x, hv2), f2_mul(l2.x, f2_mul(F2a, rr2)));
            ull n2b = f2_fma(g2.y, f2_mul(hha.y, hv2), f2_mul(l2.y, f2_mul(F2b, rr2)));
            ull n3a = f2_fma(g3.x, f2_mul(hhb.x, hv2), f2_mul(l3.x, f2_mul(F3a, rr2)));
            ull n3b = f2_fma(g3.y, f2_mul(hhb.y, hv2), f2_mul(l3.y, f2_mul(F3b, rr2)));
            t2x[u] = f2_add(w2x[2], n2a);
            t2y[u] = f2_add(w2y[2], n2b);
            t3x[u] = f2_add(w2x[3], n3a);
            t3y[u] = f2_add(w2y[3], n3b);

            // ---- x-part: smem read/modify/write ----
            const ulonglong2* __restrict__ xr =
                (const ulonglong2*)(x + ((size_t)bi * Tn + t) * In);
            ulonglong2 xv0 = ldnc2(xr + lane);          // L1 hits
            ulonglong2 xv1 = ldnc2(xr + 32 + lane);
            ulonglong2* __restrict__ Fr = F2 + bi * 64;
            ulonglong2 Fv0 = Fr[lane], Fv1 = Fr[32 + lane];

            ulonglong2 n0, n1;
            n0.x = f2_fma(g0.x, f2_mul(xv0.x, hv2), f2_mul(l0.x, f2_mul(Fv0.x, rr2)));
            n0.y = f2_fma(g0.y, f2_mul(xv0.y, hv2), f2_mul(l0.y, f2_mul(Fv0.y, rr2)));
            n1.x = f2_fma(g1.x, f2_mul(xv1.x, hv2), f2_mul(l1.x, f2_mul(Fv1.x, rr2)));
            n1.y = f2_fma(g1.y, f2_mul(xv1.y, hv2), f2_mul(l1.y, f2_mul(Fv1.y, rr2)));
            Fr[lane] = n0;
            Fr[32 + lane] = n1;

            // ---- next-step partials ----
            ull t0x = f2_add(w2x[0], n0.x), t0y = f2_add(w2y[0], n0.y);
            ull t1x = f2_add(w2x[1], n1.x), t1y = f2_add(w2y[1], n1.y);

            ull ss = f2_mul(t0x, t0x);
            ss = f2_fma(t0y, t0y, ss);
            ss = f2_fma(t1x, t1x, ss);
            ss = f2_fma(t1y, t1y, ss);
            ss = f2_fma(t2x[u], t2x[u], ss);
            ss = f2_fma(t2y[u], t2y[u], ss);
            ss = f2_fma(t3x[u], t3x[u], ss);
            ss = f2_fma(t3y[u], t3y[u], ss);
            ssp[u] = f2_fold(ss);

            const ulonglong2* __restrict__ xq =
                (const ulonglong2*)(x + ((size_t)bi * Tn + tn) * In);
            ulonglong2 xa = ldnc2(xq + lane);
            ulonglong2 xb = ldnc2(xq + 32 + lane);
            ull dx = f2_mul(xa.x, t0x);
            dx = f2_fma(xa.y, t0y, dx);
            dx = f2_fma(xb.x, t1x, dx);
            dx = f2_fma(xb.y, t1y, dx);
            dxp[u] = dx;
        }
        p0 = p1;
    }

    // ---- F writeout: x-part from smem, h-part from tw23 regs ----
    float* __restrict__ Fout = out + Bn * On + Bn * Hn;
    ulonglong2* __restrict__ Fo2 = (ulonglong2*)Fout;
#pragma unroll
    for (int u = 0; u < 4; u++) {
        const int bb = bi0 + u * 8;
        const size_t grow = (size_t)(bb * Hn + h) * (IH / 4);
        const ulonglong2* Fr = F2 + bb * 64;
        Fo2[grow + lane] = Fr[lane];
        Fo2[grow + 32 + lane] = Fr[32 + lane];
        ulonglong2 o2, o3;
        o2.x = f2_sub(t2x[u], w2x[2]); o2.y = f2_sub(t2y[u], w2y[2]);
        o3.x = f2_sub(t3x[u], w2x[3]); o3.y = f2_sub(t3y[u], w2y[3]);
        Fo2[grow + 64 + lane] = o2;
        Fo2[grow + 96 + lane] = o3;
    }

    // ---- epilogue: needs all blocks' final h (in g_h[Tn % 3] = g_h[2]) ----
    if (blockIdx.x < 64) {
        if (tid == 0) {
            const unsigned target = (unsigned)NBLK * (unsigned)Tn;
            while (ld_acquire(&g_bar) < target) __nanosleep(32);
        }
        __syncthreads();
    }

    const float* __restrict__ hfin = g_h[Tn % 3];
    if (blockIdx.x < 32) {
        const int b = blockIdx.x;
        for (int i = tid; i < Hn; i += NTHR)
            F_sm[i] = __ldcg(&hfin[b * Hn + i]);
        __syncthreads();
        const float4* hv4 = (const float4*)F_sm;
        for (int o = wid; o < On; o += 8) {
            const float4* wr = (const float4*)(Wout + (size_t)o * Hn);
            float acc = 0.f;
#pragma unroll
            for (int k = 0; k < 2; k++) {
                int j4 = k * 32 + lane;
                float4 w = __ldg(wr + j4);
                float4 hv = hv4[j4];
                acc += w.x * hv.x + w.y * hv.y + w.z * hv.z + w.w * hv.w;
            }
            acc = warp_sum(acc);
            if (lane == 0) out[b * On + o] = acc + __ldg(bout + o);
        }
    } else if (blockIdx.x < 64) {
        const int b = blockIdx.x - 32;
        for (int i = tid; i < Hn; i += NTHR)
            out[Bn * On + b * Hn + i] = __ldcg(&hfin[b * Hn + i]);
    }
}

// ---------------------------------------------------------------------------
extern "C" void kernel_launch(void* const* d_in, const int* in_sizes, int n_in,
                              void* d_out, int out_size)
{
    const float* sentence = (const float*)d_in[0];
    const float* Wl   = (const float*)d_in[1];
    const float* Wg   = (const float*)d_in[2];
    const float* W    = (const float*)d_in[3];
    const float* bias = (const float*)d_in[4];
    const float* Wout = (const float*)d_in[5];
    const float* bout = (const float*)d_in[6];
    float* out = (float*)d_out;

    const int smem = 32 * In * sizeof(float);  // 32 rows x 256 floats = 32 KB
    cudaFuncSetAttribute(persist_kernel, cudaFuncAttributeMaxDynamicSharedMemorySize, smem);

    init_kernel<<<32, 256>>>();
    persist_kernel<<<NBLK, NTHR, smem>>>(sentence, Wl, Wg, W, bias, Wout, bout, out);
}

// round 11
// speedup vs baseline: 1.1410x; 1.1010x over previous
#include <cuda_runtime.h>

#define Bn 32
#define Tn 128
#define In 256
#define Hn 256
#define IH 512
#define On 128
#define NBLK 256      // persistent blocks; 64 KB smem, <=128 regs => 2 blocks/SM
#define NTHR 256      // 8 warps

typedef unsigned long long ull;

__device__ float g_h[2][Bn * Hn];   // ping-pong hidden state
__device__ unsigned g_bar;          // monotonic grid-barrier counter (1 inc/block/step)

// ---------------------------------------------------------------------------
__global__ void init_kernel()
{
    int i = blockIdx.x * blockDim.x + threadIdx.x;
    if (i == 0) g_bar = 0u;
    for (int k = i; k < Bn * Hn; k += gridDim.x * blockDim.x) g_h[0][k] = 0.f;
}

// ---------------------------------------------------------------------------
__device__ __forceinline__ float warp_sum(float v)
{
#pragma unroll
    for (int o = 16; o > 0; o >>= 1) v += __shfl_xor_sync(0xffffffffu, v, o);
    return v;
}
__device__ __forceinline__ float tanh_fast(float v)
{
    float r; asm("tanh.approx.f32 %0, %1;" : "=f"(r) : "f"(v)); return r;
}
__device__ __forceinline__ unsigned ld_acquire(const unsigned* p)
{
    unsigned v;
    asm volatile("ld.acquire.gpu.global.u32 %0, [%1];" : "=r"(v) : "l"(p) : "memory");
    return v;
}
__device__ __forceinline__ void red_release(unsigned* p)
{
    asm volatile("red.release.gpu.global.add.u32 [%0], 1;" :: "l"(p) : "memory");
}
__device__ __forceinline__ unsigned atom_inc_cta_shared(unsigned* p)
{
    unsigned old;
    unsigned addr = (unsigned)__cvta_generic_to_shared(p);
    asm volatile("atom.acq_rel.cta.shared.add.u32 %0, [%1], 1;"
                 : "=r"(old) : "r"(addr) : "memory");
    return old;
}
__device__ __forceinline__ unsigned ld_acq_shared(unsigned* p)
{
    unsigned v;
    unsigned addr = (unsigned)__cvta_generic_to_shared(p);
    asm volatile("ld.acquire.cta.shared.u32 %0, [%1];" : "=r"(v) : "r"(addr) : "memory");
    return v;
}
__device__ __forceinline__ void st_rel_shared(unsigned* p, unsigned v)
{
    unsigned addr = (unsigned)__cvta_generic_to_shared(p);
    asm volatile("st.release.cta.shared.u32 [%0], %1;" :: "r"(addr), "r"(v) : "memory");
}
// ---- packed f32x2 primitives ----
__device__ __forceinline__ ull f2_add(ull a, ull b)
{ ull d; asm("add.rn.f32x2 %0, %1, %2;" : "=l"(d) : "l"(a), "l"(b)); return d; }
__device__ __forceinline__ ull f2_mul(ull a, ull b)
{ ull d; asm("mul.rn.f32x2 %0, %1, %2;" : "=l"(d) : "l"(a), "l"(b)); return d; }
__device__ __forceinline__ ull f2_fma(ull a, ull b, ull c)
{ ull d; asm("fma.rn.f32x2 %0, %1, %2, %3;" : "=l"(d) : "l"(a), "l"(b), "l"(c)); return d; }
__device__ __forceinline__ ull f2_bcast(float v)
{ ull d; asm("mov.b64 %0, {%1, %1};" : "=l"(d) : "f"(v)); return d; }
__device__ __forceinline__ float f2_fold(ull v)
{ float lo, hi; asm("mov.b64 {%0, %1}, %2;" : "=f"(lo), "=f"(hi) : "l"(v)); return lo + hi; }
__device__ __forceinline__ ulonglong2 ldnc2(const ulonglong2* p)
{ ulonglong2 v; asm("ld.global.nc.v2.u64 {%0,%1}, [%2];" : "=l"(v.x), "=l"(v.y) : "l"(p)); return v; }
__device__ __forceinline__ ulonglong2 ldcg2(const ulonglong2* p)
{ ulonglong2 v; asm volatile("ld.global.cg.v2.u64 {%0,%1}, [%2];" : "=l"(v.x), "=l"(v.y) : "l"(p)); return v; }

// ---------------------------------------------------------------------------
// Persistent kernel, 2 blocks/SM (R8 structure + warp-decoupled flag wait).
// Block owns h-row bid x 32 batches; F slice (32 rows x 512 = 64 KB) in smem
// as ulonglong2 pairs. Warp w handles batches w + {0,8,16,24}.
//
// Per-step, per-warp (NO __syncthreads in the loop):
//   reduce ss->rn | wait (warp 0: poll g_bar, set s_flag; others: spin s_flag)
//   B1: dots+tanh+h-store | arrive (smem atom; 8th warp -> global red)
//   B2: F writeback + fused next-step partials
// ---------------------------------------------------------------------------
__global__ __launch_bounds__(NTHR, 2) void persist_kernel(
    const float* __restrict__ x,
    const float* __restrict__ Wl,
    const float* __restrict__ Wg,
    const float* __restrict__ W,
    const float* __restrict__ bias,
    const float* __restrict__ Wout,
    const float* __restrict__ bout,
    float* __restrict__ out)
{
    extern __shared__ float F_sm[];                    // 64 KB
    ulonglong2* __restrict__ F2 = (ulonglong2*)F_sm;   // [32][128] 16B units
    __shared__ unsigned s_cnt;
    __shared__ unsigned s_flag;

    const int tid  = threadIdx.x;
    const int wid  = tid >> 5, lane = tid & 31;
    const int bi0  = wid;                      // 0..7
    const int h    = blockIdx.x;

    if (tid == 0) { s_cnt = 0u; s_flag = 0u; }

    // Pin this block's weight-row slices (pair domain).
    ulonglong2 w2[4], l2[4], g2[4];
    {
        const ulonglong2* Wp = (const ulonglong2*)(W  + (size_t)h * IH);
        const ulonglong2* Lp = (const ulonglong2*)(Wl + (size_t)h * IH);
        const ulonglong2* Gp = (const ulonglong2*)(Wg + (size_t)h * IH);
#pragma unroll
        for (int k = 0; k < 4; k++) {
            int f4 = k * 32 + lane;
            w2[k] = ldnc2(Wp + f4);
            l2[k] = ldnc2(Lp + f4);
            g2[k] = ldnc2(Gp + f4);
        }
    }
    const float bia = __ldg(bias + h);

    // Zero this warp's F rows.
    {
        ulonglong2 z; z.x = 0ull; z.y = 0ull;
#pragma unroll
        for (int u = 0; u < 4; u++) {
            ulonglong2* Fr = F2 + (bi0 + u * 8) * (IH / 4);
#pragma unroll
            for (int k = 0; k < 4; k++) Fr[k * 32 + lane] = z;
        }
    }

    // Bootstrap partials for t=0 (F=0 => tw=W).
    float ssp[4], rn[4], hn[4];
    ull dxp[4];
    {
        ull sw = f2_mul(w2[0].x, w2[0].x);
        sw = f2_fma(w2[0].y, w2[0].y, sw);
        sw = f2_fma(w2[1].x, w2[1].x, sw);
        sw = f2_fma(w2[1].y, w2[1].y, sw);
        sw = f2_fma(w2[2].x, w2[2].x, sw);
        sw = f2_fma(w2[2].y, w2[2].y, sw);
        sw = f2_fma(w2[3].x, w2[3].x, sw);
        sw = f2_fma(w2[3].y, w2[3].y, sw);
        const float ssw = f2_fold(sw);
#pragma unroll
        for (int u = 0; u < 4; u++) {
            const int bi = bi0 + u * 8;
            const ulonglong2* xr = (const ulonglong2*)(x + (size_t)bi * Tn * In);
            ulonglong2 xv0 = ldnc2(xr + lane);
            ulonglong2 xv1 = ldnc2(xr + 32 + lane);
            ull a = f2_mul(xv0.x, w2[0].x);
            a = f2_fma(xv0.y, w2[0].y, a);
            a = f2_fma(xv1.x, w2[1].x, a);
            a = f2_fma(xv1.y, w2[1].y, a);
            ssp[u] = ssw;
            dxp[u] = a;
        }
    }
    __syncthreads();   // s_cnt/s_flag init visible; only block-wide sync in kernel body

    for (int t = 0; t < Tn; t++) {
        const ulonglong2* __restrict__ hin = (const ulonglong2*)g_h[t & 1];
        float* __restrict__ hout = g_h[(t & 1) ^ 1];
        const int tn = (t + 1 < Tn) ? t + 1 : t;

        // ss reduce + rsqrt (off critical path; 4 interleaved chains).
#pragma unroll
        for (int o = 16; o > 0; o >>= 1) {
            ssp[0] += __shfl_xor_sync(0xffffffffu, ssp[0], o);
            ssp[1] += __shfl_xor_sync(0xffffffffu, ssp[1], o);
            ssp[2] += __shfl_xor_sync(0xffffffffu, ssp[2], o);
            ssp[3] += __shfl_xor_sync(0xffffffffu, ssp[3], o);
        }
#pragma unroll
        for (int u = 0; u < 4; u++) rn[u] = rsqrtf(ssp[u]);

        // ---------- warp-decoupled wait: h(t-1) published by all blocks ----------
        if (t > 0) {
            if (wid == 0) {
                if (lane == 0) {
                    const unsigned target = (unsigned)NBLK * (unsigned)t;
                    while (ld_acquire(&g_bar) < target) __nanosleep(32);
                    st_rel_shared(&s_flag, (unsigned)t);
                }
                __syncwarp();
            } else {
                while (ld_acq_shared(&s_flag) < (unsigned)t) __nanosleep(40);
            }
        }

        // ---------- B1 (critical span): dots -> h_new -> publish ----------
        ulonglong2 ha[4], hb[4];
#pragma unroll
        for (int u = 0; u < 4; u++) {          // 8 LDGs up front (MLP)
            const int bi = bi0 + u * 8;
            ha[u] = ldcg2(hin + bi * (Hn / 16) * 4 + lane);
            hb[u] = ldcg2(hin + bi * (Hn / 16) * 4 + 32 + lane);
        }
#pragma unroll
        for (int u = 0; u < 4; u++) {
            const int bi = bi0 + u * 8;
            const ulonglong2* __restrict__ Fr = F2 + bi * (IH / 4);
            ulonglong2 Fv2 = Fr[64 + lane], Fv3 = Fr[96 + lane];
            ull t2x = f2_add(w2[2].x, Fv2.x), t2y = f2_add(w2[2].y, Fv2.y);
            ull t3x = f2_add(w2[3].x, Fv3.x), t3y = f2_add(w2[3].y, Fv3.y);
            ull acc = dxp[u];
            acc = f2_fma(ha[u].x, t2x, acc);
            acc = f2_fma(ha[u].y, t2y, acc);
            acc = f2_fma(hb[u].x, t3x, acc);
            acc = f2_fma(hb[u].y, t3y, acc);
            float tot = warp_sum(f2_fold(acc));
            hn[u] = tanh_fast(tot + bia) * rn[u];
            if (lane == 0) hout[bi * Hn + h] = hn[u];
        }

        // ---------- arrive (hierarchical: smem acq_rel -> 1 global red) ----------
        if (lane == 0) {
            unsigned old = atom_inc_cta_shared(&s_cnt);
            if ((old & 7u) == 7u) red_release(&g_bar);
        }

        // ---------- B2 (off critical path): writeback + next partials ----------
#pragma unroll
        for (int u = 0; u < 4; u++) {
            const int bi = bi0 + u * 8;
            ulonglong2* __restrict__ Fr = F2 + bi * (IH / 4);
            const ull rr2 = f2_bcast(rn[u]);
            const ull hv2 = f2_bcast(hn[u]);

            const ulonglong2* __restrict__ xr =
                (const ulonglong2*)(x + ((size_t)bi * Tn + t) * In);
            ulonglong2 xv0 = ldnc2(xr + lane);          // L1 hits
            ulonglong2 xv1 = ldnc2(xr + 32 + lane);
            ulonglong2 Fv0 = Fr[lane],      Fv1 = Fr[32 + lane];
            ulonglong2 Fv2 = Fr[64 + lane], Fv3 = Fr[96 + lane];

            ulonglong2 n0, n1, n2, n3;
            n0.x = f2_fma(g2[0].x, f2_mul(xv0.x, hv2), f2_mul(l2[0].x, f2_mul(Fv0.x, rr2)));
            n0.y = f2_fma(g2[0].y, f2_mul(xv0.y, hv2), f2_mul(l2[0].y, f2_mul(Fv0.y, rr2)));
            n1.x = f2_fma(g2[1].x, f2_mul(xv1.x, hv2), f2_mul(l2[1].x, f2_mul(Fv1.x, rr2)));
            n1.y = f2_fma(g2[1].y, f2_mul(xv1.y, hv2), f2_mul(l2[1].y, f2_mul(Fv1.y, rr2)));
            n2.x = f2_fma(g2[2].x, f2_mul(ha[u].x, hv2), f2_mul(l2[2].x, f2_mul(Fv2.x, rr2)));
            n2.y = f2_fma(g2[2].y, f2_mul(ha[u].y, hv2), f2_mul(l2[2].y, f2_mul(Fv2.y, rr2)));
            n3.x = f2_fma(g2[3].x, f2_mul(hb[u].x, hv2), f2_mul(l2[3].x, f2_mul(Fv3.x, rr2)));
            n3.y = f2_fma(g2[3].y, f2_mul(hb[u].y, hv2), f2_mul(l2[3].y, f2_mul(Fv3.y, rr2)));
            Fr[lane] = n0;
            Fr[32 + lane] = n1;
            Fr[64 + lane] = n2;
            Fr[96 + lane] = n3;

            // tw_next = W + F_new; ss and dx partials in pair domain
            ull t0x = f2_add(w2[0].x, n0.x), t0y = f2_add(w2[0].y, n0.y);
            ull t1x = f2_add(w2[1].x, n1.x), t1y = f2_add(w2[1].y, n1.y);
            ull t2x = f2_add(w2[2].x, n2.x), t2y = f2_add(w2[2].y, n2.y);
            ull t3x = f2_add(w2[3].x, n3.x), t3y = f2_add(w2[3].y, n3.y);

            ull ss = f2_mul(t0x, t0x);
            ss = f2_fma(t0y, t0y, ss);
            ss = f2_fma(t1x, t1x, ss);
            ss = f2_fma(t1y, t1y, ss);
            ss = f2_fma(t2x, t2x, ss);
            ss = f2_fma(t2y, t2y, ss);
            ss = f2_fma(t3x, t3x, ss);
            ss = f2_fma(t3y, t3y, ss);
            ssp[u] = f2_fold(ss);

            const ulonglong2* __restrict__ xq =
                (const ulonglong2*)(x + ((size_t)bi * Tn + tn) * In);
            ulonglong2 xa = ldnc2(xq + lane);
            ulonglong2 xb = ldnc2(xq + 32 + lane);
            ull dx = f2_mul(xa.x, t0x);
            dx = f2_fma(xa.y, t0y, dx);
            dx = f2_fma(xb.x, t1x, dx);
            dx = f2_fma(xb.y, t1y, dx);
            dxp[u] = dx;
        }
    }

    // ---- F writeout (warp-private rows; no sync needed) ----
    float* __restrict__ Fout = out + Bn * On + Bn * Hn;
    ulonglong2* __restrict__ Fo2 = (ulonglong2*)Fout;
#pragma unroll
    for (int u = 0; u < 4; u++) {
        const int bb = bi0 + u * 8;
        const int grow = bb * Hn + h;
        const ulonglong2* Fr = F2 + bb * (IH / 4);
#pragma unroll
        for (int k = 0; k < 4; k++) {
            int f4 = k * 32 + lane;
            Fo2[(size_t)grow * (IH / 4) + f4] = Fr[f4];
        }
    }

    // ---- epilogue: needs all blocks' final h ----
    if (blockIdx.x < 64) {
        if (tid == 0) {
            const unsigned target = (unsigned)NBLK * (unsigned)Tn;
            while (ld_acquire(&g_bar) < target) __nanosleep(32);
        }
        __syncthreads();
    }

    if (blockIdx.x < 32) {
        const int b = blockIdx.x;
        for (int i = tid; i < Hn; i += NTHR)
            F_sm[i] = __ldcg(&g_h[0][b * Hn + i]);   // T even -> final h in buf 0
        __syncthreads();
        const float4* hv4 = (const float4*)F_sm;
        for (int o = wid; o < On; o += 8) {
            const float4* wr = (const float4*)(Wout + (size_t)o * Hn);
            float acc = 0.f;
#pragma unroll
            for (int k = 0; k < 2; k++) {
                int j4 = k * 32 + lane;
                float4 w = __ldg(wr + j4);
                float4 hv = hv4[j4];
                acc += w.x * hv.x + w.y * hv.y + w.z * hv.z + w.w * hv.w;
            }
            acc = warp_sum(acc);
            if (lane == 0) out[b * On + o] = acc + __ldg(bout + o);
        }
    } else if (blockIdx.x < 64) {
        const int b = blockIdx.x - 32;
        for (int i = tid; i < Hn; i += NTHR)
            out[Bn * On + b * Hn + i] = __ldcg(&g_h[0][b * Hn + i]);
    }
}

// ---------------------------------------------------------------------------
extern "C" void kernel_launch(void* const* d_in, const int* in_sizes, int n_in,
                              void* d_out, int out_size)
{
    const float* sentence = (const float*)d_in[0];
    const float* Wl   = (const float*)d_in[1];
    const float* Wg   = (const float*)d_in[2];
    const float* W    = (const float*)d_in[3];
    const float* bias = (const float*)d_in[4];
    const float* Wout = (const float*)d_in[5];
    const float* bout = (const float*)d_in[6];
    float* out = (float*)d_out;

    const int smem = 32 * IH * sizeof(float);  // 65536
    cudaFuncSetAttribute(persist_kernel, cudaFuncAttributeMaxDynamicSharedMemorySize, smem);

    init_kernel<<<32, 256>>>();
    persist_kernel<<<NBLK, NTHR, smem>>>(sentence, Wl, Wg, W, bias, Wout, bout, out);
}

// round 12
// speedup vs baseline: 1.1645x; 1.0205x over previous
#include <cuda_runtime.h>

#define Bn 32
#define Tn 128
#define In 256
#define Hn 256
#define IH 512
#define On 128
#define NBLK 256      // persistent blocks; 64 KB smem, <=128 regs => 2 blocks/SM
#define NTHR 256      // 8 warps

typedef unsigned long long ull;

__device__ float g_h[2][Bn * Hn];   // ping-pong hidden state
__device__ unsigned g_bar;          // monotonic grid-barrier counter (1 inc/block/step)

// ---------------------------------------------------------------------------
__global__ void init_kernel()
{
    int i = blockIdx.x * blockDim.x + threadIdx.x;
    if (i == 0) g_bar = 0u;
    for (int k = i; k < Bn * Hn; k += gridDim.x * blockDim.x) g_h[0][k] = 0.f;
}

// ---------------------------------------------------------------------------
__device__ __forceinline__ float warp_sum(float v)
{
#pragma unroll
    for (int o = 16; o > 0; o >>= 1) v += __shfl_xor_sync(0xffffffffu, v, o);
    return v;
}
__device__ __forceinline__ float tanh_fast(float v)
{
    float r; asm("tanh.approx.f32 %0, %1;" : "=f"(r) : "f"(v)); return r;
}
__device__ __forceinline__ unsigned ld_acquire(const unsigned* p)
{
    unsigned v;
    asm volatile("ld.acquire.gpu.global.u32 %0, [%1];" : "=r"(v) : "l"(p) : "memory");
    return v;
}
__device__ __forceinline__ void red_release(unsigned* p)
{
    asm volatile("red.release.gpu.global.add.u32 [%0], 1;" :: "l"(p) : "memory");
}
__device__ __forceinline__ unsigned atom_inc_cta_shared(unsigned* p)
{
    unsigned old;
    unsigned addr = (unsigned)__cvta_generic_to_shared(p);
    asm volatile("atom.acq_rel.cta.shared.add.u32 %0, [%1], 1;"
                 : "=r"(old) : "r"(addr) : "memory");
    return old;
}
// ---- packed f32x2 primitives ----
__device__ __forceinline__ ull f2_add(ull a, ull b)
{ ull d; asm("add.rn.f32x2 %0, %1, %2;" : "=l"(d) : "l"(a), "l"(b)); return d; }
__device__ __forceinline__ ull f2_mul(ull a, ull b)
{ ull d; asm("mul.rn.f32x2 %0, %1, %2;" : "=l"(d) : "l"(a), "l"(b)); return d; }
__device__ __forceinline__ ull f2_fma(ull a, ull b, ull c)
{ ull d; asm("fma.rn.f32x2 %0, %1, %2, %3;" : "=l"(d) : "l"(a), "l"(b), "l"(c)); return d; }
__device__ __forceinline__ ull f2_bcast(float v)
{ ull d; asm("mov.b64 %0, {%1, %1};" : "=l"(d) : "f"(v)); return d; }
__device__ __forceinline__ float f2_fold(ull v)
{ float lo, hi; asm("mov.b64 {%0, %1}, %2;" : "=f"(lo), "=f"(hi) : "l"(v)); return lo + hi; }
__device__ __forceinline__ ulonglong2 ldnc2(const ulonglong2* p)
{ ulonglong2 v; asm("ld.global.nc.v2.u64 {%0,%1}, [%2];" : "=l"(v.x), "=l"(v.y) : "l"(p)); return v; }
__device__ __forceinline__ ulonglong2 ldcg2(const ulonglong2* p)
{ ulonglong2 v; asm volatile("ld.global.cg.v2.u64 {%0,%1}, [%2];" : "=l"(v.x), "=l"(v.y) : "l"(p)); return v; }

// ---------------------------------------------------------------------------
// Persistent kernel, 2 blocks/SM (R8 structure, h-part writeback fused into
// B1 so the F h-half is LDS-loaded exactly once per step).
// Block owns h-row bid x 32 batches; F slice (32 rows x 512 = 64 KB) in smem.
// Warp w handles batches w + {0,8,16,24}; lane slice: 16B unit k*32+lane.
//
// Step: [reduce ss->rn | leader-poll + bar.sync wait |
//   B1 per batch: LDS Fv2/3 -> dot -> tanh -> STG h -> n2/n3 STS + ssh fold |
//   arrive (smem atom, 8th warp -> global red) |
//   B2 per batch: x-part writeback + next-step ss/dx partials]
// ---------------------------------------------------------------------------
__global__ __launch_bounds__(NTHR, 2) void persist_kernel(
    const float* __restrict__ x,
    const float* __restrict__ Wl,
    const float* __restrict__ Wg,
    const float* __restrict__ W,
    const float* __restrict__ bias,
    const float* __restrict__ Wout,
    const float* __restrict__ bout,
    float* __restrict__ out)
{
    extern __shared__ float F_sm[];                    // 64 KB
    ulonglong2* __restrict__ F2 = (ulonglong2*)F_sm;   // [32][128] 16B units
    __shared__ unsigned s_cnt;

    const int tid  = threadIdx.x;
    const int wid  = tid >> 5, lane = tid & 31;
    const int bi0  = wid;                      // 0..7
    const int h    = blockIdx.x;

    if (tid == 0) s_cnt = 0u;

    // Pin this block's weight-row slices (pair domain).
    ulonglong2 w2[4], l2[4], g2[4];
    {
        const ulonglong2* Wp = (const ulonglong2*)(W  + (size_t)h * IH);
        const ulonglong2* Lp = (const ulonglong2*)(Wl + (size_t)h * IH);
        const ulonglong2* Gp = (const ulonglong2*)(Wg + (size_t)h * IH);
#pragma unroll
        for (int k = 0; k < 4; k++) {
            int f4 = k * 32 + lane;
            w2[k] = ldnc2(Wp + f4);
            l2[k] = ldnc2(Lp + f4);
            g2[k] = ldnc2(Gp + f4);
        }
    }
    const float bia = __ldg(bias + h);

    // Zero this warp's F rows.
    {
        ulonglong2 z; z.x = 0ull; z.y = 0ull;
#pragma unroll
        for (int u = 0; u < 4; u++) {
            ulonglong2* Fr = F2 + (bi0 + u * 8) * (IH / 4);
#pragma unroll
            for (int k = 0; k < 4; k++) Fr[k * 32 + lane] = z;
        }
    }

    // Bootstrap partials for t=0 (F=0 => tw=W).
    float ssp[4], rn[4], hn[4], ssh[4];
    ull dxp[4];
    {
        ull sw = f2_mul(w2[0].x, w2[0].x);
        sw = f2_fma(w2[0].y, w2[0].y, sw);
        sw = f2_fma(w2[1].x, w2[1].x, sw);
        sw = f2_fma(w2[1].y, w2[1].y, sw);
        sw = f2_fma(w2[2].x, w2[2].x, sw);
        sw = f2_fma(w2[2].y, w2[2].y, sw);
        sw = f2_fma(w2[3].x, w2[3].x, sw);
        sw = f2_fma(w2[3].y, w2[3].y, sw);
        const float ssw = f2_fold(sw);
#pragma unroll
        for (int u = 0; u < 4; u++) {
            const int bi = bi0 + u * 8;
            const ulonglong2* xr = (const ulonglong2*)(x + (size_t)bi * Tn * In);
            ulonglong2 xv0 = ldnc2(xr + lane);
            ulonglong2 xv1 = ldnc2(xr + 32 + lane);
            ull a = f2_mul(xv0.x, w2[0].x);
            a = f2_fma(xv0.y, w2[0].y, a);
            a = f2_fma(xv1.x, w2[1].x, a);
            a = f2_fma(xv1.y, w2[1].y, a);
            ssp[u] = ssw;
            dxp[u] = a;
        }
    }

    for (int t = 0; t < Tn; t++) {
        const ulonglong2* __restrict__ hin = (const ulonglong2*)g_h[t & 1];
        float* __restrict__ hout = g_h[(t & 1) ^ 1];
        const int tn = (t + 1 < Tn) ? t + 1 : t;

        // ss reduce + rsqrt (off critical path; 4 interleaved chains).
#pragma unroll
        for (int o = 16; o > 0; o >>= 1) {
            ssp[0] += __shfl_xor_sync(0xffffffffu, ssp[0], o);
            ssp[1] += __shfl_xor_sync(0xffffffffu, ssp[1], o);
            ssp[2] += __shfl_xor_sync(0xffffffffu, ssp[2], o);
            ssp[3] += __shfl_xor_sync(0xffffffffu, ssp[3], o);
        }
#pragma unroll
        for (int u = 0; u < 4; u++) rn[u] = rsqrtf(ssp[u]);

        // ---------- wait: h(t-1) published by all blocks ----------
        if (tid == 0) {
            const unsigned target = (unsigned)NBLK * (unsigned)t;
            while (ld_acquire(&g_bar) < target) __nanosleep(32);
        }
        __syncthreads();

        // ---------- B1: per batch, dot -> publish h -> fused h-part writeback ----------
        ulonglong2 ha[4], hb[4];
#pragma unroll
        for (int u = 0; u < 4; u++) {          // 8 LDGs up front (MLP)
            const int bi = bi0 + u * 8;
            ha[u] = ldcg2(hin + bi * (Hn / 16) * 4 + lane);
            hb[u] = ldcg2(hin + bi * (Hn / 16) * 4 + 32 + lane);
        }
#pragma unroll
        for (int u = 0; u < 4; u++) {
            const int bi = bi0 + u * 8;
            ulonglong2* __restrict__ Fr = F2 + bi * (IH / 4);
            ulonglong2 Fv2 = Fr[64 + lane], Fv3 = Fr[96 + lane];
            ull t2x = f2_add(w2[2].x, Fv2.x), t2y = f2_add(w2[2].y, Fv2.y);
            ull t3x = f2_add(w2[3].x, Fv3.x), t3y = f2_add(w2[3].y, Fv3.y);
            ull acc = dxp[u];
            acc = f2_fma(ha[u].x, t2x, acc);
            acc = f2_fma(ha[u].y, t2y, acc);
            acc = f2_fma(hb[u].x, t3x, acc);
            acc = f2_fma(hb[u].y, t3y, acc);
            float tot = warp_sum(f2_fold(acc));
            const float hv = tanh_fast(tot + bia) * rn[u];
            hn[u] = hv;
            if (lane == 0) hout[bi * Hn + h] = hv;

            // fused h-part writeback (Fv2/3, ha/hb still live — no reload)
            const ull rr2 = f2_bcast(rn[u]);
            const ull hv2 = f2_bcast(hv);
            ulonglong2 n2, n3;
            n2.x = f2_fma(g2[2].x, f2_mul(ha[u].x, hv2), f2_mul(l2[2].x, f2_mul(Fv2.x, rr2)));
            n2.y = f2_fma(g2[2].y, f2_mul(ha[u].y, hv2), f2_mul(l2[2].y, f2_mul(Fv2.y, rr2)));
            n3.x = f2_fma(g2[3].x, f2_mul(hb[u].x, hv2), f2_mul(l2[3].x, f2_mul(Fv3.x, rr2)));
            n3.y = f2_fma(g2[3].y, f2_mul(hb[u].y, hv2), f2_mul(l2[3].y, f2_mul(Fv3.y, rr2)));
            Fr[64 + lane] = n2;
            Fr[96 + lane] = n3;

            // h-part contribution to next-step ss (tw23_next = w + n)
            ull u2x = f2_add(w2[2].x, n2.x), u2y = f2_add(w2[2].y, n2.y);
            ull u3x = f2_add(w2[3].x, n3.x), u3y = f2_add(w2[3].y, n3.y);
            ull sh = f2_mul(u2x, u2x);
            sh = f2_fma(u2y, u2y, sh);
            sh = f2_fma(u3x, u3x, sh);
            sh = f2_fma(u3y, u3y, sh);
            ssh[u] = f2_fold(sh);
        }

        // ---------- arrive (hierarchical: smem acq_rel -> 1 global red) ----------
        if (lane == 0) {
            unsigned old = atom_inc_cta_shared(&s_cnt);
            if ((old & 7u) == 7u) red_release(&g_bar);
        }

        // ---------- B2 (off critical path): x-part writeback + partials ----------
#pragma unroll
        for (int u = 0; u < 4; u++) {
            const int bi = bi0 + u * 8;
            ulonglong2* __restrict__ Fr = F2 + bi * (IH / 4);
            const ull rr2 = f2_bcast(rn[u]);
            const ull hv2 = f2_bcast(hn[u]);

            const ulonglong2* __restrict__ xr =
                (const ulonglong2*)(x + ((size_t)bi * Tn + t) * In);
            ulonglong2 xv0 = ldnc2(xr + lane);          // L1 hits
            ulonglong2 xv1 = ldnc2(xr + 32 + lane);
            ulonglong2 Fv0 = Fr[lane], Fv1 = Fr[32 + lane];

            ulonglong2 n0, n1;
            n0.x = f2_fma(g2[0].x, f2_mul(xv0.x, hv2), f2_mul(l2[0].x, f2_mul(Fv0.x, rr2)));
            n0.y = f2_fma(g2[0].y, f2_mul(xv0.y, hv2), f2_mul(l2[0].y, f2_mul(Fv0.y, rr2)));
            n1.x = f2_fma(g2[1].x, f2_mul(xv1.x, hv2), f2_mul(l2[1].x, f2_mul(Fv1.x, rr2)));
            n1.y = f2_fma(g2[1].y, f2_mul(xv1.y, hv2), f2_mul(l2[1].y, f2_mul(Fv1.y, rr2)));
            Fr[lane] = n0;
            Fr[32 + lane] = n1;

            // next-step partials: x-part tw, ss = ss_x + ssh, dx = x(t+1)·tw01
            ull t0x = f2_add(w2[0].x, n0.x), t0y = f2_add(w2[0].y, n0.y);
            ull t1x = f2_add(w2[1].x, n1.x), t1y = f2_add(w2[1].y, n1.y);

            ull ss = f2_mul(t0x, t0x);
            ss = f2_fma(t0y, t0y, ss);
            ss = f2_fma(t1x, t1x, ss);
            ss = f2_fma(t1y, t1y, ss);
            ssp[u] = f2_fold(ss) + ssh[u];

            const ulonglong2* __restrict__ xq =
                (const ulonglong2*)(x + ((size_t)bi * Tn + tn) * In);
            ulonglong2 xa = ldnc2(xq + lane);
            ulonglong2 xb = ldnc2(xq + 32 + lane);
            ull dx = f2_mul(xa.x, t0x);
            dx = f2_fma(xa.y, t0y, dx);
            dx = f2_fma(xb.x, t1x, dx);
            dx = f2_fma(xb.y, t1y, dx);
            dxp[u] = dx;
        }
    }

    // ---- F writeout (warp-private rows) ----
    float* __restrict__ Fout = out + Bn * On + Bn * Hn;
    ulonglong2* __restrict__ Fo2 = (ulonglong2*)Fout;
#pragma unroll
    for (int u = 0; u < 4; u++) {
        const int bb = bi0 + u * 8;
        const int grow = bb * Hn + h;
        const ulonglong2* Fr = F2 + bb * (IH / 4);
#pragma unroll
        for (int k = 0; k < 4; k++) {
            int f4 = k * 32 + lane;
            Fo2[(size_t)grow * (IH / 4) + f4] = Fr[f4];
        }
    }

    // ---- epilogue: needs all blocks' final h ----
    if (blockIdx.x < 64) {
        if (tid == 0) {
            const unsigned target = (unsigned)NBLK * (unsigned)Tn;
            while (ld_acquire(&g_bar) < target) __nanosleep(32);
        }
        __syncthreads();
    }

    if (blockIdx.x < 32) {
        const int b = blockIdx.x;
        for (int i = tid; i < Hn; i += NTHR)
            F_sm[i] = __ldcg(&g_h[0][b * Hn + i]);   // T even -> final h in buf 0
        __syncthreads();
        const float4* hv4 = (const float4*)F_sm;
        for (int o = wid; o < On; o += 8) {
            const float4* wr = (const float4*)(Wout + (size_t)o * Hn);
            float acc = 0.f;
#pragma unroll
            for (int k = 0; k < 2; k++) {
                int j4 = k * 32 + lane;
                float4 w = __ldg(wr + j4);
                float4 hv = hv4[j4];
                acc += w.x * hv.x + w.y * hv.y + w.z * hv.z + w.w * hv.w;
            }
            acc = warp_sum(acc);
            if (lane == 0) out[b * On + o] = acc + __ldg(bout + o);
        }
    } else if (blockIdx.x < 64) {
        const int b = blockIdx.x - 32;
        for (int i = tid; i < Hn; i += NTHR)
            out[Bn * On + b * Hn + i] = __ldcg(&g_h[0][b * Hn + i]);
    }
}

// ---------------------------------------------------------------------------
extern "C" void kernel_launch(void* const* d_in, const int* in_sizes, int n_in,
                              void* d_out, int out_size)
{
    const float* sentence = (const float*)d_in[0];
    const float* Wl   = (const float*)d_in[1];
    const float* Wg   = (const float*)d_in[2];
    const float* W    = (const float*)d_in[3];
    const float* bias = (const float*)d_in[4];
    const float* Wout = (const float*)d_in[5];
    const float* bout = (const float*)d_in[6];
    float* out = (float*)d_out;

    const int smem = 32 * IH * sizeof(float);  // 65536
    cudaFuncSetAttribute(persist_kernel, cudaFuncAttributeMaxDynamicSharedMemorySize, smem);

    init_kernel<<<32, 256>>>();
    persist_kernel<<<NBLK, NTHR, smem>>>(sentence, Wl, Wg, W, bias, Wout, bout, out);
}